// round 11
// baseline (speedup 1.0000x reference)
#include <cuda_runtime.h>
#include <cuda_bf16.h>
#include <cstdint>

// RelationProbe via mma.sync.m16n8k16 (bf16 3-term split, f32 accum),
// W in registers, z streamed through warp-private cp.async double buffers.
// R11 = R10 + coalesced output: per-stage outputs staged into the unused
// 32 B/row smem pad region, then written as one 256 B float2 burst per
// warp per plane (fully coalesced STG), 2 block barriers per stage.

#define THREADS 128
#define STAGE_ROWS 64                 // per CTA-stage (16 per warp)
#define ROW_PITCH 288                 // 256 B data + 32 B pad
#define WARP_BUF (16 * ROW_PITCH)     // 4608 B per warp per parity

static __device__ __forceinline__ uint32_t smem_u32(const void* p) {
    uint32_t a;
    asm("{ .reg .u64 t; cvta.to.shared.u64 t, %1; cvt.u32.u64 %0, t; }" : "=r"(a) : "l"(p));
    return a;
}

static __device__ __forceinline__ uint64_t make_evict_first_policy() {
    uint64_t pol;
    asm("createpolicy.fractional.L2::evict_first.b64 %0, 1.0;" : "=l"(pol));
    return pol;
}

static __device__ __forceinline__ void cp_async16_pol(uint32_t dst, const void* src,
                                                      uint64_t pol) {
    asm volatile("cp.async.cg.shared.global.L2::cache_hint [%0], [%1], 16, %2;"
                 :: "r"(dst), "l"(src), "l"(pol) : "memory");
}
static __device__ __forceinline__ void cp_commit() {
    asm volatile("cp.async.commit_group;" ::: "memory");
}
template<int N> static __device__ __forceinline__ void cp_wait() {
    asm volatile("cp.async.wait_group %0;" :: "n"(N) : "memory");
}

// Pack two f32 into bf16x2 (hi) and the residual into bf16x2 (lo).
static __device__ __forceinline__ uint32_t pack_split(float x, float y, uint32_t& lo) {
    __nv_bfloat162 h = __float22bfloat162_rn(make_float2(x, y));
    uint32_t u = *reinterpret_cast<uint32_t*>(&h);
    float ex = __uint_as_float(u << 16);
    float ey = __uint_as_float(u & 0xffff0000u);
    __nv_bfloat162 l = __float22bfloat162_rn(make_float2(x - ex, y - ey));
    lo = *reinterpret_cast<uint32_t*>(&l);
    return u;
}

static __device__ __forceinline__ void mma_bf16(float* d,
                                                uint32_t a0, uint32_t a1,
                                                uint32_t a2, uint32_t a3,
                                                uint32_t b0, uint32_t b1) {
    asm volatile(
        "mma.sync.aligned.m16n8k16.row.col.f32.bf16.bf16.f32 "
        "{%0,%1,%2,%3}, {%4,%5,%6,%7}, {%8,%9}, {%0,%1,%2,%3};"
        : "+f"(d[0]), "+f"(d[1]), "+f"(d[2]), "+f"(d[3])
        : "r"(a0), "r"(a1), "r"(a2), "r"(a3), "r"(b0), "r"(b1));
}

__global__ void __launch_bounds__(THREADS, 6)
relation_probe_co(const float* __restrict__ zg,    // z: [B][64] f32
                  const float* __restrict__ Wg,    // [4][6][64]
                  const float* __restrict__ bg,    // [4][6]
                  const int* __restrict__ pidx,    // [B]
                  float* __restrict__ out,         // [4][B]
                  int B)
{
    // [warp][parity] private z buffers; out staging lives in the pad bytes
    // (256..287 of each row) of parity-0 buffers: plane p, col c (0..63) at
    // zbuf[p][0] + (c>>3)*ROW_PITCH + 256 + (c&7)*4. cp.async never touches pads.
    __shared__ __align__(16) char zbuf[4][2][WARP_BUF];
    __shared__ float sbias0[3][4], sbias1[3][4];   // [nt][q]

    const int tid  = threadIdx.x;
    const int lane = tid & 31;
    const int wid  = tid >> 5;
    const int g = lane >> 2;     // fragment row group 0..7
    const int q = lane & 3;      // fragment quad col  0..3

    // ---- one-time prologue: W fragments in registers (pair-major heads) ----
    uint32_t Bhi[4][3][2], Blo[4][3][2];
    #pragma unroll
    for (int nt = 0; nt < 3; nt++) {
        int n = nt * 8 + g;
        int rr = n & 3, pp = n >> 2;
        const float* wb = Wg + (rr * 6 + pp) * 64;
        #pragma unroll
        for (int kt = 0; kt < 4; kt++) {
            int kc = kt * 16 + q * 2;
            Bhi[kt][nt][0] = pack_split(wb[kc],     wb[kc + 1], Blo[kt][nt][0]);
            Bhi[kt][nt][1] = pack_split(wb[kc + 8], wb[kc + 9], Blo[kt][nt][1]);
        }
    }
    if (tid < 12) {
        int nt = tid / 4, qq = tid & 3;
        int n0 = nt * 8 + qq * 2;
        int n1 = n0 + 1;
        sbias0[nt][qq] = (n0 < 24) ? bg[(n0 & 3) * 6 + (n0 >> 2)] : 0.0f;
        sbias1[nt][qq] = (n1 < 24) ? bg[(n1 & 3) * 6 + (n1 >> 2)] : 0.0f;
    }
    __syncthreads();

    const uint64_t pol = make_evict_first_policy();
    const uint32_t buf0 = smem_u32(&zbuf[wid][0][0]);
    const uint32_t buf1 = smem_u32(&zbuf[wid][1][0]);

    const int S = B / STAGE_ROWS;        // total CTA-stages
    const int G = gridDim.x;

    // pad-staging address for (plane, col)
    #define PAD_SLOT(pl, c) \
        ((float*)(&zbuf[(pl)][0][(((c) >> 3) * ROW_PITCH) + 256 + (((c) & 7) * 4)]))

    #define ISSUE_WSTAGE(st, dstb)                                                   \
    do {                                                                             \
        const char* src = (const char*)zg                                            \
            + ((size_t)(st) * STAGE_ROWS + wid * 16) * 256;                          \
        _Pragma("unroll")                                                            \
        for (int j_ = 0; j_ < 8; j_++) {                                             \
            int flat = lane + j_ * 32;                                               \
            int row_ = flat >> 4;                                                    \
            int c_   = flat & 15;                                                    \
            cp_async16_pol((dstb) + row_ * ROW_PITCH + c_ * 16,                      \
                           src + (size_t)row_ * 256 + c_ * 16, pol);                 \
        }                                                                            \
        cp_commit();                                                                 \
    } while (0)

    int s = blockIdx.x;
    if (s < S) ISSUE_WSTAGE(s, buf0);

    for (int i = 0; ; i++) {
        if (s >= S) break;
        const int snext = s + G;
        const uint32_t nxt = (i & 1) ? buf0 : buf1;
        if (snext < S) {
            ISSUE_WSTAGE(snext, nxt);
            cp_wait<1>();
        } else {
            cp_wait<0>();
        }
        __syncthreads();   // data ready; prior write-phase done before new deposits

        // ---- compute stage s: rows s*64 + wid*16 + {g, g+8} ----
        const char* sb = (const char*)zbuf[wid][i & 1];
        const char* r1 = sb + g * ROW_PITCH;
        const char* r2 = r1 + 8 * ROW_PITCH;

        const int row1 = s * STAGE_ROWS + wid * 16 + g;
        const int row2 = row1 + 8;
        const int p1 = __ldcs(pidx + row1);
        const int p2 = __ldcs(pidx + row2);

        float acc[3][4];
        #pragma unroll
        for (int nt = 0; nt < 3; nt++) {
            float b0v = sbias0[nt][q], b1v = sbias1[nt][q];
            acc[nt][0] = b0v; acc[nt][1] = b1v;
            acc[nt][2] = b0v; acc[nt][3] = b1v;
        }

        #pragma unroll
        for (int kt = 0; kt < 4; kt++) {
            float2 f0 = *(const float2*)(r1 + kt * 64 + q * 8);
            float2 f1 = *(const float2*)(r2 + kt * 64 + q * 8);
            float2 f2 = *(const float2*)(r1 + kt * 64 + 32 + q * 8);
            float2 f3 = *(const float2*)(r2 + kt * 64 + 32 + q * 8);

            uint32_t ah[4], al[4];
            ah[0] = pack_split(f0.x, f0.y, al[0]);
            ah[1] = pack_split(f1.x, f1.y, al[1]);
            ah[2] = pack_split(f2.x, f2.y, al[2]);
            ah[3] = pack_split(f3.x, f3.y, al[3]);
            #pragma unroll
            for (int nt = 0; nt < 3; nt++) {
                mma_bf16(acc[nt], ah[0], ah[1], ah[2], ah[3],
                         Bhi[kt][nt][0], Bhi[kt][nt][1]);
                mma_bf16(acc[nt], al[0], al[1], al[2], al[3],
                         Bhi[kt][nt][0], Bhi[kt][nt][1]);
                mma_bf16(acc[nt], ah[0], ah[1], ah[2], ah[3],
                         Blo[kt][nt][0], Blo[kt][nt][1]);
            }
        }

        // ---- deposit selected heads into pad staging (plane = relation) ----
        // Per row, q = 2*(p&1) deposits planes {0,1}, q = 2*(p&1)+1 planes {2,3}.
        {
            unsigned sel = (unsigned)(q - 2 * (p1 & 1));
            int nt = p1 >> 1;
            float va = (nt == 0) ? acc[0][0] : (nt == 1) ? acc[1][0] : acc[2][0];
            float vb = (nt == 0) ? acc[0][1] : (nt == 1) ? acc[1][1] : acc[2][1];
            if (sel < 2u) {
                int lr = wid * 16 + g;
                *PAD_SLOT(2 * sel,     lr) = va;
                *PAD_SLOT(2 * sel + 1, lr) = vb;
            }
        }
        {
            unsigned sel = (unsigned)(q - 2 * (p2 & 1));
            int nt = p2 >> 1;
            float va = (nt == 0) ? acc[0][2] : (nt == 1) ? acc[1][2] : acc[2][2];
            float vb = (nt == 0) ? acc[0][3] : (nt == 1) ? acc[1][3] : acc[2][3];
            if (sel < 2u) {
                int lr = wid * 16 + g + 8;
                *PAD_SLOT(2 * sel,     lr) = va;
                *PAD_SLOT(2 * sel + 1, lr) = vb;
            }
        }

        __syncthreads();   // all deposits visible

        // ---- write phase: warp w writes plane w, 64 consecutive floats ----
        {
            int c = 2 * lane;
            float2 v = *(const float2*)PAD_SLOT(wid, c);
            __stcs((float2*)(out + (size_t)wid * B + (size_t)s * STAGE_ROWS + c), v);
        }

        s = snext;
    }
    #undef ISSUE_WSTAGE
    #undef PAD_SLOT
}

extern "C" void kernel_launch(void* const* d_in, const int* in_sizes, int n_in,
                              void* d_out, int out_size)
{
    // Bind by element count: z = B*64 (largest), W = 1536, b = 24, pair_idx = B.
    int zi = -1, ii = -1, wi = -1, bi = -1;
    for (int i = 0; i < n_in; i++) {
        if (in_sizes[i] == 1536) { wi = i; continue; }
        if (in_sizes[i] == 24)   { bi = i; continue; }
        if (zi < 0 || in_sizes[i] > in_sizes[zi]) zi = i;
    }
    for (int i = 0; i < n_in; i++) {
        if (i == zi || i == wi || i == bi) continue;
        ii = i;
    }

    const float* zg = (const float*)d_in[zi];
    const float* Wg = (const float*)d_in[wi];
    const float* bg = (const float*)d_in[bi];
    const int*   pi = (const int*)d_in[ii];
    float*       op = (float*)d_out;
    const int B = in_sizes[ii];

    int nsm = 148;
    cudaDeviceGetAttribute(&nsm, cudaDevAttrMultiProcessorCount, 0);
    int grid = nsm * 6;                      // persistent: 6 CTAs per SM
    const int S = B / STAGE_ROWS;
    if (grid > S) grid = S;

    relation_probe_co<<<grid, THREADS>>>(zg, Wg, bg, pi, op, B);
}

// round 12
// speedup vs baseline: 1.0326x; 1.0326x over previous
#include <cuda_runtime.h>
#include <cuda_bf16.h>
#include <cstdint>

// RelationProbe via mma.sync.m16n8k16 (bf16 3-term split, f32 accum),
// W in registers, z streamed through warp-private cp.async double buffers.
// R12 = R8 (best: 180.1us, DRAM 82%) + prefetch.global.L2 of stage s+2:
// depth-2 prefetch at zero smem cost — cp.async then hits L2 instead of DRAM.

#define THREADS 128
#define STAGE_ROWS 64                 // per CTA-stage (16 per warp)
#define ROW_PITCH 288                 // 256 B data + 32 B pad (bank-free)
#define WARP_BUF (16 * ROW_PITCH)     // 4608 B per warp per parity

static __device__ __forceinline__ uint32_t smem_u32(const void* p) {
    uint32_t a;
    asm("{ .reg .u64 t; cvta.to.shared.u64 t, %1; cvt.u32.u64 %0, t; }" : "=r"(a) : "l"(p));
    return a;
}

static __device__ __forceinline__ void cp_async16(uint32_t dst, const void* src) {
    asm volatile("cp.async.cg.shared.global [%0], [%1], 16;" :: "r"(dst), "l"(src) : "memory");
}
static __device__ __forceinline__ void cp_commit() {
    asm volatile("cp.async.commit_group;" ::: "memory");
}
template<int N> static __device__ __forceinline__ void cp_wait() {
    asm volatile("cp.async.wait_group %0;" :: "n"(N) : "memory");
}
static __device__ __forceinline__ void prefetch_l2(const void* p) {
    asm volatile("prefetch.global.L2 [%0];" :: "l"(p));
}

// Pack two f32 into bf16x2 (hi) and the residual into bf16x2 (lo).
static __device__ __forceinline__ uint32_t pack_split(float x, float y, uint32_t& lo) {
    __nv_bfloat162 h = __float22bfloat162_rn(make_float2(x, y));
    uint32_t u = *reinterpret_cast<uint32_t*>(&h);
    float ex = __uint_as_float(u << 16);
    float ey = __uint_as_float(u & 0xffff0000u);
    __nv_bfloat162 l = __float22bfloat162_rn(make_float2(x - ex, y - ey));
    lo = *reinterpret_cast<uint32_t*>(&l);
    return u;
}

static __device__ __forceinline__ void mma_bf16(float* d,
                                                uint32_t a0, uint32_t a1,
                                                uint32_t a2, uint32_t a3,
                                                uint32_t b0, uint32_t b1) {
    asm volatile(
        "mma.sync.aligned.m16n8k16.row.col.f32.bf16.bf16.f32 "
        "{%0,%1,%2,%3}, {%4,%5,%6,%7}, {%8,%9}, {%0,%1,%2,%3};"
        : "+f"(d[0]), "+f"(d[1]), "+f"(d[2]), "+f"(d[3])
        : "r"(a0), "r"(a1), "r"(a2), "r"(a3), "r"(b0), "r"(b1));
}

__global__ void __launch_bounds__(THREADS, 6)
relation_probe_pf(const float* __restrict__ zg,    // z: [B][64] f32
                  const float* __restrict__ Wg,    // [4][6][64]
                  const float* __restrict__ bg,    // [4][6]
                  const int* __restrict__ pidx,    // [B]
                  float* __restrict__ out,         // [4][B]
                  int B)
{
    // [warp][parity] private buffers
    __shared__ __align__(16) char zbuf[4][2][WARP_BUF];
    __shared__ float sbias0[3][4], sbias1[3][4];   // [nt][q]

    const int tid  = threadIdx.x;
    const int lane = tid & 31;
    const int wid  = tid >> 5;
    const int g = lane >> 2;     // fragment row group 0..7
    const int q = lane & 3;      // fragment quad col  0..3

    // ---- one-time prologue: W fragments in registers (pair-major heads) ----
    uint32_t Bhi[4][3][2], Blo[4][3][2];
    #pragma unroll
    for (int nt = 0; nt < 3; nt++) {
        int n = nt * 8 + g;
        int rr = n & 3, pp = n >> 2;
        const float* wb = Wg + (rr * 6 + pp) * 64;
        #pragma unroll
        for (int kt = 0; kt < 4; kt++) {
            int kc = kt * 16 + q * 2;
            Bhi[kt][nt][0] = pack_split(wb[kc],     wb[kc + 1], Blo[kt][nt][0]);
            Bhi[kt][nt][1] = pack_split(wb[kc + 8], wb[kc + 9], Blo[kt][nt][1]);
        }
    }
    if (tid < 12) {
        int nt = tid / 4, qq = tid & 3;
        int n0 = nt * 8 + qq * 2;
        int n1 = n0 + 1;
        sbias0[nt][qq] = (n0 < 24) ? bg[(n0 & 3) * 6 + (n0 >> 2)] : 0.0f;
        sbias1[nt][qq] = (n1 < 24) ? bg[(n1 & 3) * 6 + (n1 >> 2)] : 0.0f;
    }
    __syncthreads();   // only block barrier in the kernel

    const uint32_t buf0 = smem_u32(&zbuf[wid][0][0]);
    const uint32_t buf1 = smem_u32(&zbuf[wid][1][0]);

    const int S = B / STAGE_ROWS;        // total CTA-stages
    const int G = gridDim.x;

    // This warp's 16 rows of stage st.
    #define ISSUE_WSTAGE(st, dstb)                                                   \
    do {                                                                             \
        const char* src = (const char*)zg                                            \
            + ((size_t)(st) * STAGE_ROWS + wid * 16) * 256;                          \
        _Pragma("unroll")                                                            \
        for (int j_ = 0; j_ < 8; j_++) {                                             \
            int flat = lane + j_ * 32;                                               \
            int row_ = flat >> 4;                                                    \
            int c_   = flat & 15;                                                    \
            cp_async16((dstb) + row_ * ROW_PITCH + c_ * 16,                          \
                       src + (size_t)row_ * 256 + c_ * 16);                          \
        }                                                                            \
        cp_commit();                                                                 \
    } while (0)

    int s = blockIdx.x;
    if (s < S) ISSUE_WSTAGE(s, buf0);
    // prime L2 for stage s+G
    if (s + G < S) {
        const char* pf = (const char*)zg
            + ((size_t)(s + G) * STAGE_ROWS + wid * 16) * 256;
        prefetch_l2(pf + lane * 128);
    }

    for (int i = 0; ; i++) {
        if (s >= S) break;
        const int snext = s + G;
        const uint32_t nxt = (i & 1) ? buf0 : buf1;
        if (snext < S) {
            ISSUE_WSTAGE(snext, nxt);
            // depth-2: start DRAM fetch for stage s+2G now (32 x 128B lines)
            const int s2 = snext + G;
            if (s2 < S) {
                const char* pf = (const char*)zg
                    + ((size_t)s2 * STAGE_ROWS + wid * 16) * 256;
                prefetch_l2(pf + lane * 128);
            }
            cp_wait<1>();          // this warp's stage s complete
        } else {
            cp_wait<0>();
        }
        __syncwarp();              // cross-lane visibility within the warp

        // ---- compute stage s: rows s*64 + wid*16 + {g, g+8} ----
        const char* sb = (const char*)zbuf[wid][i & 1];
        const char* r1 = sb + g * ROW_PITCH;
        const char* r2 = r1 + 8 * ROW_PITCH;

        const int row1 = s * STAGE_ROWS + wid * 16 + g;
        const int row2 = row1 + 8;
        const int p1 = pidx[row1];
        const int p2 = pidx[row2];

        float acc[3][4];
        #pragma unroll
        for (int nt = 0; nt < 3; nt++) {
            float b0v = sbias0[nt][q], b1v = sbias1[nt][q];
            acc[nt][0] = b0v; acc[nt][1] = b1v;
            acc[nt][2] = b0v; acc[nt][3] = b1v;
        }

        #pragma unroll
        for (int kt = 0; kt < 4; kt++) {
            float2 f0 = *(const float2*)(r1 + kt * 64 + q * 8);
            float2 f1 = *(const float2*)(r2 + kt * 64 + q * 8);
            float2 f2 = *(const float2*)(r1 + kt * 64 + 32 + q * 8);
            float2 f3 = *(const float2*)(r2 + kt * 64 + 32 + q * 8);

            uint32_t ah[4], al[4];
            ah[0] = pack_split(f0.x, f0.y, al[0]);
            ah[1] = pack_split(f1.x, f1.y, al[1]);
            ah[2] = pack_split(f2.x, f2.y, al[2]);
            ah[3] = pack_split(f3.x, f3.y, al[3]);
            #pragma unroll
            for (int nt = 0; nt < 3; nt++) {
                mma_bf16(acc[nt], ah[0], ah[1], ah[2], ah[3],
                         Bhi[kt][nt][0], Bhi[kt][nt][1]);
                mma_bf16(acc[nt], al[0], al[1], al[2], al[3],
                         Bhi[kt][nt][0], Bhi[kt][nt][1]);
                mma_bf16(acc[nt], ah[0], ah[1], ah[2], ah[3],
                         Blo[kt][nt][0], Blo[kt][nt][1]);
            }
        }

        // ---- epilogue: heads n = 4p + r; thread owns cols 2q,2q+1 of
        // N-tile p>>1; writes iff sel = q - 2*(p&1) in {0,1}
        {
            unsigned sel = (unsigned)(q - 2 * (p1 & 1));
            int nt = p1 >> 1;
            float va = (nt == 0) ? acc[0][0] : (nt == 1) ? acc[1][0] : acc[2][0];
            float vb = (nt == 0) ? acc[0][1] : (nt == 1) ? acc[1][1] : acc[2][1];
            if (sel < 2u) {
                out[(size_t)(2 * sel)     * B + row1] = va;
                out[(size_t)(2 * sel + 1) * B + row1] = vb;
            }
        }
        {
            unsigned sel = (unsigned)(q - 2 * (p2 & 1));
            int nt = p2 >> 1;
            float va = (nt == 0) ? acc[0][2] : (nt == 1) ? acc[1][2] : acc[2][2];
            float vb = (nt == 0) ? acc[0][3] : (nt == 1) ? acc[1][3] : acc[2][3];
            if (sel < 2u) {
                out[(size_t)(2 * sel)     * B + row2] = va;
                out[(size_t)(2 * sel + 1) * B + row2] = vb;
            }
        }

        __syncwarp();   // all lanes done reading before buffer reuse
        s = snext;
    }
    #undef ISSUE_WSTAGE
}

extern "C" void kernel_launch(void* const* d_in, const int* in_sizes, int n_in,
                              void* d_out, int out_size)
{
    // Bind by element count: z = B*64 (largest), W = 1536, b = 24, pair_idx = B.
    int zi = -1, ii = -1, wi = -1, bi = -1;
    for (int i = 0; i < n_in; i++) {
        if (in_sizes[i] == 1536) { wi = i; continue; }
        if (in_sizes[i] == 24)   { bi = i; continue; }
        if (zi < 0 || in_sizes[i] > in_sizes[zi]) zi = i;
    }
    for (int i = 0; i < n_in; i++) {
        if (i == zi || i == wi || i == bi) continue;
        ii = i;
    }

    const float* zg = (const float*)d_in[zi];
    const float* Wg = (const float*)d_in[wi];
    const float* bg = (const float*)d_in[bi];
    const int*   pi = (const int*)d_in[ii];
    float*       op = (float*)d_out;
    const int B = in_sizes[ii];

    int nsm = 148;
    cudaDeviceGetAttribute(&nsm, cudaDevAttrMultiProcessorCount, 0);
    int grid = nsm * 6;                      // persistent: 6 CTAs per SM
    const int S = B / STAGE_ROWS;
    if (grid > S) grid = S;

    relation_probe_pf<<<grid, THREADS>>>(zg, Wg, bg, pi, op, B);
}